// round 13
// baseline (speedup 1.0000x reference)
#include <cuda_runtime.h>
#include <cuda_fp16.h>
#include <stdint.h>
#include <math.h>

#define Bb   2
#define Tt   2048
#define Cc   1024
#define Hh   8
#define KVh  4
#define Dd   128
#define WINs 512
#define HIDm 4096
#define Mrows (Bb*Tt)   // 4096

// ---------------- scratch ----------------
__device__ __half g_h   [Mrows*Cc];
__device__ __half g_qh  [Mrows*Hh*Dd];
__device__ __half g_kh  [Mrows*KVh*Dd];
__device__ __half g_vh  [Mrows*KVh*Dd];
__device__ __half g_attnh[Mrows*Hh*Dd];
__device__ float  g_x2  [Mrows*Cc];
__device__ __half g_gateh[Mrows*HIDm];
__device__ __half g_act [Mrows*HIDm];
// fp16 weights in NATIVE [K][N] layout (no transpose)
__device__ __half g_wq[1048576];
__device__ __half g_wk[524288];
__device__ __half g_wv[524288];
__device__ __half g_wo[1048576];
__device__ __half g_wg[4194304];
__device__ __half g_wu[4194304];
__device__ __half g_wd[4194304];

// ---------------- helpers ----------------
__device__ __forceinline__ void mma_f16(float* d, const uint32_t* a, const uint32_t* b) {
    asm volatile(
        "mma.sync.aligned.m16n8k16.row.col.f32.f16.f16.f32 "
        "{%0,%1,%2,%3},{%4,%5,%6,%7},{%8,%9},{%0,%1,%2,%3};"
        : "+f"(d[0]), "+f"(d[1]), "+f"(d[2]), "+f"(d[3])
        : "r"(a[0]), "r"(a[1]), "r"(a[2]), "r"(a[3]),
          "r"(b[0]), "r"(b[1]));
}
__device__ __forceinline__ void ldm_x4(uint32_t* r, uint32_t addr) {
    asm volatile("ldmatrix.sync.aligned.m8n8.x4.shared.b16 {%0,%1,%2,%3}, [%4];"
        : "=r"(r[0]), "=r"(r[1]), "=r"(r[2]), "=r"(r[3]) : "r"(addr));
}
__device__ __forceinline__ void ldm_x4_t(uint32_t* r, uint32_t addr) {
    asm volatile("ldmatrix.sync.aligned.m8n8.x4.trans.shared.b16 {%0,%1,%2,%3}, [%4];"
        : "=r"(r[0]), "=r"(r[1]), "=r"(r[2]), "=r"(r[3]) : "r"(addr));
}

#define CP16(dst, src) \
    asm volatile("cp.async.cg.shared.global [%0], [%1], 16;" :: "r"(dst), "l"(src))
#define CP_COMMIT() asm volatile("cp.async.commit_group;")

// softcap: 50*tanh(s/50)
__device__ __forceinline__ float softcap50(float s) {
    float x = s * 0.02f;
    float x2 = x * x;
    float t;
    if (x2 <= 0.09f) {
        t = x * (1.0f + x2 * (-0.333333333f + x2 * (0.133333333f + x2 * (-0.053968254f))));
    } else {
        t = tanhf(x);
    }
    return 50.0f * t;
}

// ---------------- fp32 -> fp16 streaming convert (MLP=8) ---------------------
// Each thread loads 8 independent float4 (batched), converts, stores 8 uint2.
// n4 must be divisible by blockDim.x*8 = 2048 per block.
__global__ void cvt_kernel(const float4* __restrict__ in, __half* __restrict__ out, int n4)
{
    int base = blockIdx.x * (blockDim.x * 8) + threadIdx.x;
    float4 v[8];
    #pragma unroll
    for (int i = 0; i < 8; i++)
        v[i] = in[base + i * blockDim.x];
    #pragma unroll
    for (int i = 0; i < 8; i++) {
        __half2 h0 = __floats2half2_rn(v[i].x, v[i].y);
        __half2 h1 = __floats2half2_rn(v[i].z, v[i].w);
        *(uint2*)(out + (size_t)(base + i * blockDim.x) * 4) =
            make_uint2(*(uint32_t*)&h0, *(uint32_t*)&h1);
    }
}

// ---------------- rmsnorm -> fp16 ----------------
__global__ void rmsnorm_h_kernel(const float* __restrict__ x,
                                 const float* __restrict__ scale,
                                 __half* __restrict__ y)
{
    int row = blockIdx.x;
    const float4* xr = (const float4*)(x + (size_t)row * Cc);
    float4 v = xr[threadIdx.x];
    float ss = v.x*v.x + v.y*v.y + v.z*v.z + v.w*v.w;
    #pragma unroll
    for (int o = 16; o; o >>= 1) ss += __shfl_xor_sync(0xffffffffu, ss, o);
    __shared__ float wsum[8];
    if ((threadIdx.x & 31) == 0) wsum[threadIdx.x >> 5] = ss;
    __syncthreads();
    if (threadIdx.x < 8) {
        float t = wsum[threadIdx.x];
        #pragma unroll
        for (int o = 4; o; o >>= 1) t += __shfl_xor_sync(0xffu, t, o);
        if (threadIdx.x == 0) wsum[0] = t;
    }
    __syncthreads();
    float inv = rsqrtf(wsum[0] * (1.0f / Cc) + 1e-6f);
    float4 sc = ((const float4*)scale)[threadIdx.x];
    __half2 h0 = __floats2half2_rn(v.x * inv * (1.f + sc.x), v.y * inv * (1.f + sc.y));
    __half2 h1 = __floats2half2_rn(v.z * inv * (1.f + sc.z), v.w * inv * (1.f + sc.w));
    uint2 u = make_uint2(*(uint32_t*)&h0, *(uint32_t*)&h1);
    *(uint2*)(y + (size_t)row * Cc + threadIdx.x * 4) = u;
}

// ---------------- FP16 GEMM: A[M,K]@B[K,N], B native layout, trans-ldmatrix --
// MODE 0: C=acc (float)       MODE 1: C=acc+Res (float)
// MODE 3: C=silu(acc) (half)  MODE 4: C=acc*Res (half,half)  MODE 5: C=acc (half)
#define PAH 40
#define A_HBYTES (128*PAH*2)       // 10240
#define B_HBYTES (32*128*2)        // 8192
#define STAGE_HB (A_HBYTES + B_HBYTES)   // 18432
#define H_STAGES 3
#define HGEMM_SMEM (H_STAGES*STAGE_HB)   // 55296

template<int MODE, typename OT, typename RT>
__device__ __forceinline__ void hgemm_tile(
    const __half* __restrict__ A, const __half* __restrict__ Bkn,
    const RT* __restrict__ Res, OT* __restrict__ C,
    int NB, int NC, int K, int m0, int n0)
{
    extern __shared__ __half smh[];
    uint32_t smb;
    asm("{ .reg .u64 t; cvta.to.shared.u64 t, %1; cvt.u32.u64 %0, t; }"
        : "=r"(smb) : "l"(smh));

    int tid  = threadIdx.x;
    int lane = tid & 31, warp = tid >> 5;
    int wm = (warp & 1) * 64;
    int wn = (warp >> 1) * 32;
    int g = lane >> 2, c = lane & 3;
    int lane16 = lane & 15;
    int lhi = (lane & 16) >> 1;
    int m_ = lane >> 3, r_ = lane & 7;
    int tb = (m_ >> 1) * 8 + r_;       // k-row within 16-block for trans B

    uint32_t offA[4][2];
    #pragma unroll
    for (int mt = 0; mt < 4; mt++)
        #pragma unroll
        for (int ks = 0; ks < 2; ks++) {
            int row = wm + mt * 16 + lane16;
            int kx = ks * 16 + lhi;
            offA[mt][ks] = (uint32_t)(row * PAH + kx) * 2u;
        }
    uint32_t offB[2][2];
    #pragma unroll
    for (int bi = 0; bi < 2; bi++)
        #pragma unroll
        for (int ks = 0; ks < 2; ks++) {
            int k = ks * 16 + tb;
            int nch = (wn >> 3) + bi * 2 + (m_ & 1);
            offB[bi][ks] = (uint32_t)A_HBYTES + (uint32_t)(k * 256 + (((nch) ^ r_) << 4));
        }

    const __half* Ag = A + (size_t)m0 * K;

    float acc[4][4][4];
    #pragma unroll
    for (int i = 0; i < 4; i++)
        #pragma unroll
        for (int j = 0; j < 4; j++)
            #pragma unroll
            for (int r = 0; r < 4; r++) acc[i][j][r] = 0.f;

    int ntiles = K >> 5;

    int lra = tid >> 2, lca = tid & 3;
    int lrb = tid >> 3, lcb = (tid & 7) * 2;
    auto load_stage = [&](int s, int kc) {
        uint32_t base = smb + s * STAGE_HB;
        #pragma unroll
        for (int i = 0; i < 2; i++) {
            int r = lra + i * 64;
            CP16(base + r * 80 + lca * 16, Ag + (size_t)r * K + kc * 32 + lca * 8);
        }
        uint32_t bb = base + A_HBYTES;
        const __half* Bs = Bkn + (size_t)(kc * 32 + lrb) * NB + n0;
        #pragma unroll
        for (int i = 0; i < 2; i++) {
            int ch = lcb + i;
            CP16(bb + lrb * 256 + ((ch ^ (lrb & 7)) << 4), Bs + ch * 8);
        }
    };

    load_stage(0, 0); CP_COMMIT();
    load_stage(1, 1); CP_COMMIT();

    for (int kt = 0; kt < ntiles; kt++) {
        asm volatile("cp.async.wait_group 1;");
        __syncthreads();

        int pf = kt + H_STAGES - 1;
        if (pf < ntiles) load_stage(pf % H_STAGES, pf);
        CP_COMMIT();

        uint32_t sbase = smb + (kt % H_STAGES) * STAGE_HB;
        #pragma unroll
        for (int ks = 0; ks < 2; ks++) {
            uint32_t bf[4][2];
            #pragma unroll
            for (int bi = 0; bi < 2; bi++) {
                uint32_t r[4];
                ldm_x4_t(r, sbase + offB[bi][ks]);
                bf[2 * bi][0] = r[0]; bf[2 * bi + 1][0] = r[1];
                bf[2 * bi][1] = r[2]; bf[2 * bi + 1][1] = r[3];
            }
            #pragma unroll
            for (int mt = 0; mt < 4; mt++) {
                uint32_t af[4];
                ldm_x4(af, sbase + offA[mt][ks]);
                #pragma unroll
                for (int nt = 0; nt < 4; nt++)
                    mma_f16(acc[mt][nt], af, bf[nt]);
            }
        }
    }

    #pragma unroll
    for (int mt = 0; mt < 4; mt++) {
        int r0 = m0 + wm + mt * 16 + g;
        #pragma unroll
        for (int nt = 0; nt < 4; nt++) {
            int cl = n0 + wn + nt * 8 + 2 * c;
            #pragma unroll
            for (int half_i = 0; half_i < 2; half_i++) {
                int rr = r0 + half_i * 8;
                float v0 = acc[mt][nt][half_i * 2 + 0];
                float v1 = acc[mt][nt][half_i * 2 + 1];
                size_t idx = (size_t)rr * NC + cl;
                if (MODE == 0) {
                    *(float2*)((float*)C + idx) = make_float2(v0, v1);
                } else if (MODE == 1) {
                    v0 += ((const float*)Res)[idx];
                    v1 += ((const float*)Res)[idx + 1];
                    *(float2*)((float*)C + idx) = make_float2(v0, v1);
                } else if (MODE == 3) {
                    v0 = v0 / (1.f + expf(-v0));
                    v1 = v1 / (1.f + expf(-v1));
                    *(__half2*)((__half*)C + idx) = __floats2half2_rn(v0, v1);
                } else if (MODE == 4) {
                    __half2 gh = *(const __half2*)((const __half*)Res + idx);
                    float2 gf = __half22float2(gh);
                    v0 *= gf.x; v1 *= gf.y;
                    *(__half2*)((__half*)C + idx) = __floats2half2_rn(v0, v1);
                } else if (MODE == 5) {
                    *(__half2*)((__half*)C + idx) = __floats2half2_rn(v0, v1);
                }
            }
        }
    }
}

template<int MODE, typename OT, typename RT>
__global__ __launch_bounds__(256, 2) void hgemm_kernel(
    const __half* __restrict__ A, const __half* __restrict__ Bkn,
    const RT* __restrict__ Res, OT* __restrict__ C, int N, int K)
{
    hgemm_tile<MODE, OT, RT>(A, Bkn, Res, C, N, N, K, blockIdx.y * 128, blockIdx.x * 128);
}

__global__ __launch_bounds__(256, 2) void qkv_h_kernel(
    const __half* __restrict__ A,
    const __half* __restrict__ Bq, const __half* __restrict__ Bk,
    const __half* __restrict__ Bv,
    __half* __restrict__ Cq, __half* __restrict__ Ck, __half* __restrict__ Cv,
    int K)
{
    int nb = blockIdx.x, m0 = blockIdx.y * 128;
    if (nb < 8)
        hgemm_tile<5, __half, float>(A, Bq, (const float*)nullptr, Cq, 1024, 1024, K, m0, nb * 128);
    else if (nb < 12)
        hgemm_tile<5, __half, float>(A, Bk, (const float*)nullptr, Ck, 512, 512, K, m0, (nb - 8) * 128);
    else
        hgemm_tile<5, __half, float>(A, Bv, (const float*)nullptr, Cv, 512, 512, K, m0, (nb - 12) * 128);
}

// ---------------- RoPE: fp16 in-place (+ q prescale) -------------------------
__global__ void rope_kernel(__half* __restrict__ q, __half* __restrict__ k)
{
    int row = blockIdx.x;
    int t = row & (Tt - 1);
    const float qscale = 0.08838834764831845f;
    __shared__ float s_sin[64], s_cos[64];
    if (threadIdx.x < 64) {
        float inv = expf(-logf(10000.0f) * (2.0f * threadIdx.x) / 128.0f);
        float ang = (float)t * inv;
        s_sin[threadIdx.x] = sinf(ang);
        s_cos[threadIdx.x] = cosf(ang);
    }
    __syncthreads();
    for (int p = threadIdx.x; p < 512; p += 256) {
        int head = p >> 6, i = p & 63;
        __half* base = q + (size_t)row * 1024 + head * 128;
        float x1 = __half2float(base[i]), x2 = __half2float(base[i + 64]);
        float s = s_sin[i], c = s_cos[i];
        base[i]      = __float2half_rn((x1 * c - x2 * s) * qscale);
        base[i + 64] = __float2half_rn((x2 * c + x1 * s) * qscale);
    }
    for (int p = threadIdx.x; p < 256; p += 256) {
        int head = p >> 6, i = p & 63;
        __half* base = k + (size_t)row * 512 + head * 128;
        float x1 = __half2float(base[i]), x2 = __half2float(base[i + 64]);
        float s = s_sin[i], c = s_cos[i];
        base[i]      = __float2half_rn(x1 * c - x2 * s);
        base[i + 64] = __float2half_rn(x2 * c + x1 * s);
    }
}

// ---------------- attention: 128-q tile, register Q/P, V via trans-ldmatrix --
// smem halves: Ks[2][64*128] @ 0,8192; Vs[2][64*128] @ 16384,24576
#define ATTN_SMEM (32768 * 2)   // 65536 B
__global__ __launch_bounds__(256, 1) void attn_kernel(
    const __half* __restrict__ Q, const __half* __restrict__ K,
    const __half* __restrict__ V, __half* __restrict__ O)
{
    extern __shared__ __half sma[];
    uint32_t smb;
    asm("{ .reg .u64 t; cvta.to.shared.u64 t, %1; cvt.u32.u64 %0, t; }"
        : "=r"(smb) : "l"(sma));

    int qb = blockIdx.x, h = blockIdx.y, b = blockIdx.z;
    int q0 = qb * 128;
    int tid = threadIdx.x, lane = tid & 31, warp = tid >> 5;
    int g = lane >> 2, c = lane & 3;
    int lane16 = lane & 15;
    int hb = (lane & 16) >> 4;
    int m_ = lane >> 3, r_ = lane & 7;
    int tb = (m_ >> 1) * 8 + r_;

    const __half* Qg = Q + (size_t)(b * Tt + q0 + 16 * warp) * 1024 + h * 128;
    uint32_t qf[8][4];
    #pragma unroll
    for (int ks = 0; ks < 8; ks++) {
        int kx = 16 * ks + 2 * c;
        qf[ks][0] = *(const uint32_t*)(Qg + (size_t)g * 1024 + kx);
        qf[ks][1] = *(const uint32_t*)(Qg + (size_t)(g + 8) * 1024 + kx);
        qf[ks][2] = *(const uint32_t*)(Qg + (size_t)g * 1024 + kx + 8);
        qf[ks][3] = *(const uint32_t*)(Qg + (size_t)(g + 8) * 1024 + kx + 8);
    }

    float Oacc[16][4];
    #pragma unroll
    for (int i = 0; i < 16; i++)
        #pragma unroll
        for (int j = 0; j < 4; j++) Oacc[i][j] = 0.f;
    float rm0 = -1e30f, rm1 = -1e30f, rl0 = 0.f, rl1 = 0.f;

    int kvh = h & 3;
    const __half* Kg = K + (size_t)b * Tt * 512 + kvh * 128;
    const __half* Vg = V + (size_t)b * Tt * 512 + kvh * 128;

    uint32_t voff[8];
    #pragma unroll
    for (int bi = 0; bi < 8; bi++) {
        int dch = bi * 2 + (m_ & 1);
        voff[bi] = (uint32_t)(tb * 128 + ((dch ^ r_) << 3)) * 2u;
    }

    int jlo = (2 * qb - 8 > 0) ? 2 * qb - 8 : 0;
    int jhi = 2 * qb + 1;

    auto load_kv = [&](int s, int k0) {
        #pragma unroll
        for (int p = 0; p < 4; p++) {
            int idx = tid + p * 256;
            int row = idx >> 4, ch = idx & 15;
            CP16(smb + (uint32_t)(s * 8192 + row * 128 + ((ch ^ (row & 7)) << 3)) * 2u,
                 Kg + (size_t)(k0 + row) * 512 + ch * 8);
        }
        #pragma unroll
        for (int p = 0; p < 4; p++) {
            int idx = tid + p * 256;
            int row = idx >> 4, ch = idx & 15;
            CP16(smb + (uint32_t)(16384 + s * 8192 + row * 128 + ((ch ^ (row & 7)) << 3)) * 2u,
                 Vg + (size_t)(k0 + row) * 512 + ch * 8);
        }
    };

    load_kv(0, jlo * 64); CP_COMMIT();

    int qt0 = q0 + 16 * warp + g;
    int qt1 = qt0 + 8;

    for (int jt = jlo; jt <= jhi; jt++) {
        int s = (jt - jlo) & 1;
        int k0 = jt * 64;

        asm volatile("cp.async.wait_group 0;");
        __syncthreads();
        if (jt < jhi) { load_kv(s ^ 1, k0 + 64); }
        CP_COMMIT();

        float sacc[8][4];
        #pragma unroll
        for (int i = 0; i < 8; i++)
            #pragma unroll
            for (int j = 0; j < 4; j++) sacc[i][j] = 0.f;
        #pragma unroll
        for (int ks = 0; ks < 8; ks++) {
            int chunk = 2 * ks + hb;
            uint32_t bf[8][2];
            #pragma unroll
            for (int bi = 0; bi < 4; bi++) {
                int colK = bi * 16 + lane16;
                uint32_t r[4];
                ldm_x4(r, smb + (uint32_t)(s * 8192 + colK * 128 +
                                           ((chunk ^ (colK & 7)) << 3)) * 2u);
                bf[2 * bi][0] = r[0]; bf[2 * bi + 1][0] = r[1];
                bf[2 * bi][1] = r[2]; bf[2 * bi + 1][1] = r[3];
            }
            #pragma unroll
            for (int nt = 0; nt < 8; nt++)
                mma_f16(sacc[nt], qf[ks], bf[nt]);
        }

        float pm0 = -INFINITY, pm1 = -INFINITY;
        #pragma unroll
        for (int nt = 0; nt < 8; nt++) {
            #pragma unroll
            for (int e = 0; e < 4; e++) {
                int ktg = k0 + nt * 8 + 2 * c + (e & 1);
                int qt = (e >> 1) ? qt1 : qt0;
                float sv = softcap50(sacc[nt][e]);
                bool ok = (ktg <= qt) && (qt - ktg < WINs);
                sv = ok ? sv : -INFINITY;
                sacc[nt][e] = sv;
                if (e >> 1) pm1 = fmaxf(pm1, sv); else pm0 = fmaxf(pm0, sv);
            }
        }
        pm0 = fmaxf(pm0, __shfl_xor_sync(0xffffffffu, pm0, 1));
        pm0 = fmaxf(pm0, __shfl_xor_sync(0xffffffffu, pm0, 2));
        pm1 = fmaxf(pm1, __shfl_xor_sync(0xffffffffu, pm1, 1));
        pm1 = fmaxf(pm1, __shfl_xor_sync(0xffffffffu, pm1, 2));

        float mn0 = fmaxf(rm0, pm0);
        float mn1 = fmaxf(rm1, pm1);
        float al0 = __expf(rm0 - mn0); rm0 = mn0;
        float al1 = __expf(rm1 - mn1); rm1 = mn1;

        uint32_t ph0[8], ph1[8];
        float ps0 = 0.f, ps1 = 0.f;
        #pragma unroll
        for (int nt = 0; nt < 8; nt++) {
            __half2 h0 = __floats2half2_rn(__expf(sacc[nt][0] - mn0),
                                           __expf(sacc[nt][1] - mn0));
            __half2 h1 = __floats2half2_rn(__expf(sacc[nt][2] - mn1),
                                           __expf(sacc[nt][3] - mn1));
            float2 f0 = __half22float2(h0), f1 = __half22float2(h1);
            ps0 += f0.x + f0.y;
            ps1 += f1.x + f1.y;
            ph0[nt] = *(uint32_t*)&h0;
            ph1[nt] = *(uint32_t*)&h1;
        }
        ps0 += __shfl_xor_sync(0xffffffffu, ps0, 1);
        ps0 += __shfl_xor_sync(0xffffffffu, ps0, 2);
        ps1 += __shfl_xor_sync(0xffffffffu, ps1, 1);
        ps1 += __shfl_xor_sync(0xffffffffu, ps1, 2);
        rl0 = rl0 * al0 + ps0;
        rl1 = rl1 * al1 + ps1;

        #pragma unroll
        for (int i = 0; i < 16; i++) {
            Oacc[i][0] *= al0; Oacc[i][1] *= al0;
            Oacc[i][2] *= al1; Oacc[i][3] *= al1;
        }

        uint32_t vstage = smb + (uint32_t)(16384 + s * 8192) * 2u;
        #pragma unroll
        for (int ks = 0; ks < 4; ks++) {
            uint32_t af[4] = { ph0[2 * ks], ph1[2 * ks], ph0[2 * ks + 1], ph1[2 * ks + 1] };
            uint32_t krow = (uint32_t)(ks * 16 * 128) * 2u;
            uint32_t vb[16][2];
            #pragma unroll
            for (int bi = 0; bi < 8; bi++) {
                uint32_t r[4];
                ldm_x4_t(r, vstage + krow + voff[bi]);
                vb[2 * bi][0] = r[0]; vb[2 * bi + 1][0] = r[1];
                vb[2 * bi][1] = r[2]; vb[2 * bi + 1][1] = r[3];
            }
            #pragma unroll
            for (int nt = 0; nt < 16; nt++)
                mma_f16(Oacc[nt], af, vb[nt]);
        }
    }

    float li0 = 1.f / rl0, li1 = 1.f / rl1;
    __half* Og = O + (size_t)(b * Tt + q0 + 16 * warp) * 1024 + h * 128;
    #pragma unroll
    for (int nt = 0; nt < 16; nt++) {
        int col = nt * 8 + 2 * c;
        *(__half2*)(Og + (size_t)g * 1024 + col) =
            __floats2half2_rn(Oacc[nt][0] * li0, Oacc[nt][1] * li0);
        *(__half2*)(Og + (size_t)(g + 8) * 1024 + col) =
            __floats2half2_rn(Oacc[nt][2] * li1, Oacc[nt][3] * li1);
    }
}

// ---------------- launch ----------------
extern "C" void kernel_launch(void* const* d_in, const int* in_sizes, int n_in,
                              void* d_out, int out_size)
{
    const float* x        = (const float*)d_in[0];
    const float* q_kernel = (const float*)d_in[1];
    const float* k_kernel = (const float*)d_in[2];
    const float* v_kernel = (const float*)d_in[3];
    const float* out_kern = (const float*)d_in[4];
    const float* attn_sc  = (const float*)d_in[5];
    const float* mlp_sc   = (const float*)d_in[6];
    const float* gate_k   = (const float*)d_in[7];
    const float* up_k     = (const float*)d_in[8];
    const float* down_k   = (const float*)d_in[9];
    float* out = (float*)d_out;

    __half *p_h, *p_attnh, *p_act, *p_qh, *p_kh, *p_vh, *p_gateh;
    float *p_x2;
    __half *w_q, *w_k, *w_v, *w_o, *w_g, *w_u, *w_d;
    cudaGetSymbolAddress((void**)&p_h,     g_h);
    cudaGetSymbolAddress((void**)&p_qh,    g_qh);
    cudaGetSymbolAddress((void**)&p_kh,    g_kh);
    cudaGetSymbolAddress((void**)&p_vh,    g_vh);
    cudaGetSymbolAddress((void**)&p_attnh, g_attnh);
    cudaGetSymbolAddress((void**)&p_x2,    g_x2);
    cudaGetSymbolAddress((void**)&p_gateh, g_gateh);
    cudaGetSymbolAddress((void**)&p_act,   g_act);
    cudaGetSymbolAddress((void**)&w_q,     g_wq);
    cudaGetSymbolAddress((void**)&w_k,     g_wk);
    cudaGetSymbolAddress((void**)&w_v,     g_wv);
    cudaGetSymbolAddress((void**)&w_o,     g_wo);
    cudaGetSymbolAddress((void**)&w_g,     g_wg);
    cudaGetSymbolAddress((void**)&w_u,     g_wu);
    cudaGetSymbolAddress((void**)&w_d,     g_wd);

    cudaFuncSetAttribute(attn_kernel, cudaFuncAttributeMaxDynamicSharedMemorySize, ATTN_SMEM);
    cudaFuncSetAttribute(qkv_h_kernel, cudaFuncAttributeMaxDynamicSharedMemorySize, HGEMM_SMEM);
    cudaFuncSetAttribute((hgemm_kernel<1, float, float>),   cudaFuncAttributeMaxDynamicSharedMemorySize, HGEMM_SMEM);
    cudaFuncSetAttribute((hgemm_kernel<3, __half, float>),  cudaFuncAttributeMaxDynamicSharedMemorySize, HGEMM_SMEM);
    cudaFuncSetAttribute((hgemm_kernel<4, __half, __half>), cudaFuncAttributeMaxDynamicSharedMemorySize, HGEMM_SMEM);

    // 0) weights: streaming fp32 -> fp16 (MLP=8 per thread), native [K][N]
    cvt_kernel<<<128, 256>>>((const float4*)q_kernel, w_q, 262144);
    cvt_kernel<<<64,  256>>>((const float4*)k_kernel, w_k, 131072);
    cvt_kernel<<<64,  256>>>((const float4*)v_kernel, w_v, 131072);
    cvt_kernel<<<128, 256>>>((const float4*)out_kern, w_o, 262144);
    cvt_kernel<<<512, 256>>>((const float4*)gate_k,   w_g, 1048576);
    cvt_kernel<<<512, 256>>>((const float4*)up_k,     w_u, 1048576);
    cvt_kernel<<<512, 256>>>((const float4*)down_k,   w_d, 1048576);

    // 1) h = rmsnorm(x, attn_scale) -> fp16
    rmsnorm_h_kernel<<<Mrows, 256>>>(x, attn_sc, p_h);
    // 2) fused q/k/v projections -> fp16
    qkv_h_kernel<<<dim3(16, 32), 256, HGEMM_SMEM>>>(p_h, w_q, w_k, w_v, p_qh, p_kh, p_vh, 1024);
    // 3) rope in-place on fp16 q (prescaled) and k
    rope_kernel<<<Mrows, 256>>>(p_qh, p_kh);
    // 4) attention
    attn_kernel<<<dim3(Tt / 128, Hh, Bb), 256, ATTN_SMEM>>>(p_qh, p_kh, p_vh, p_attnh);
    // 5) out projection + residual
    hgemm_kernel<1, float, float><<<dim3(8, 32), 256, HGEMM_SMEM>>>(p_attnh, w_o, x, p_x2, 1024, 1024);
    // 6) h = rmsnorm(x2, mlp_scale) -> fp16
    rmsnorm_h_kernel<<<Mrows, 256>>>(p_x2, mlp_sc, p_h);
    // 7) gate (silu, fp16), then up * gate -> fp16 act
    hgemm_kernel<3, __half, float><<<dim3(32, 32), 256, HGEMM_SMEM>>>(p_h, w_g, (const float*)nullptr, p_gateh, HIDm, 1024);
    hgemm_kernel<4, __half, __half><<<dim3(32, 32), 256, HGEMM_SMEM>>>(p_h, w_u, p_gateh, p_act, HIDm, 1024);
    // 8) down + residual -> out
    hgemm_kernel<1, float, float><<<dim3(8, 32), 256, HGEMM_SMEM>>>(p_act, w_d, p_x2, out, 1024, HIDm);
}

// round 14
// speedup vs baseline: 1.0254x; 1.0254x over previous
#include <cuda_runtime.h>
#include <cuda_fp16.h>
#include <stdint.h>
#include <math.h>

#define Bb   2
#define Tt   2048
#define Cc   1024
#define Hh   8
#define KVh  4
#define Dd   128
#define WINs 512
#define HIDm 4096
#define Mrows (Bb*Tt)   // 4096

// ---------------- scratch ----------------
__device__ __half g_h   [Mrows*Cc];
__device__ __half g_qh  [Mrows*Hh*Dd];
__device__ __half g_kh  [Mrows*KVh*Dd];
__device__ __half g_vh  [Mrows*KVh*Dd];
__device__ __half g_attnh[Mrows*Hh*Dd];
__device__ float  g_x2  [Mrows*Cc];
__device__ __half g_gateh[Mrows*HIDm];
__device__ __half g_act [Mrows*HIDm];
// fp16 weights in NATIVE [K][N] layout (no transpose)
__device__ __half g_wq[1048576];
__device__ __half g_wk[524288];
__device__ __half g_wv[524288];
__device__ __half g_wo[1048576];
__device__ __half g_wg[4194304];
__device__ __half g_wu[4194304];
__device__ __half g_wd[4194304];

// ---------------- helpers ----------------
__device__ __forceinline__ void mma_f16(float* d, const uint32_t* a, const uint32_t* b) {
    asm volatile(
        "mma.sync.aligned.m16n8k16.row.col.f32.f16.f16.f32 "
        "{%0,%1,%2,%3},{%4,%5,%6,%7},{%8,%9},{%0,%1,%2,%3};"
        : "+f"(d[0]), "+f"(d[1]), "+f"(d[2]), "+f"(d[3])
        : "r"(a[0]), "r"(a[1]), "r"(a[2]), "r"(a[3]),
          "r"(b[0]), "r"(b[1]));
}
__device__ __forceinline__ void ldm_x4(uint32_t* r, uint32_t addr) {
    asm volatile("ldmatrix.sync.aligned.m8n8.x4.shared.b16 {%0,%1,%2,%3}, [%4];"
        : "=r"(r[0]), "=r"(r[1]), "=r"(r[2]), "=r"(r[3]) : "r"(addr));
}
__device__ __forceinline__ void ldm_x4_t(uint32_t* r, uint32_t addr) {
    asm volatile("ldmatrix.sync.aligned.m8n8.x4.trans.shared.b16 {%0,%1,%2,%3}, [%4];"
        : "=r"(r[0]), "=r"(r[1]), "=r"(r[2]), "=r"(r[3]) : "r"(addr));
}

#define CP16(dst, src) \
    asm volatile("cp.async.cg.shared.global [%0], [%1], 16;" :: "r"(dst), "l"(src))
#define CP_COMMIT() asm volatile("cp.async.commit_group;")

// softcap: 50*tanh(s/50)
__device__ __forceinline__ float softcap50(float s) {
    float x = s * 0.02f;
    float x2 = x * x;
    float t;
    if (x2 <= 0.09f) {
        t = x * (1.0f + x2 * (-0.333333333f + x2 * (0.133333333f + x2 * (-0.053968254f))));
    } else {
        t = tanhf(x);
    }
    return 50.0f * t;
}

// ---------------- fused fp32 -> fp16 convert for ALL weights (1 launch) ------
// segments (block counts): q 128 | k 64 | v 64 | o 128 | g 512 | u 512 | d 512
struct CvtArgs {
    const float4* src[7];
    __half* dst[7];
};
__global__ void cvt_all_kernel(CvtArgs a)
{
    int blk = blockIdx.x;
    int seg, lblk;
    if      (blk < 128)  { seg = 0; lblk = blk; }
    else if (blk < 192)  { seg = 1; lblk = blk - 128; }
    else if (blk < 256)  { seg = 2; lblk = blk - 192; }
    else if (blk < 384)  { seg = 3; lblk = blk - 256; }
    else if (blk < 896)  { seg = 4; lblk = blk - 384; }
    else if (blk < 1408) { seg = 5; lblk = blk - 896; }
    else                 { seg = 6; lblk = blk - 1408; }

    const float4* in = a.src[seg];
    __half* out = a.dst[seg];
    int base = lblk * (256 * 8) + threadIdx.x;
    float4 v[8];
    #pragma unroll
    for (int i = 0; i < 8; i++)
        v[i] = in[base + i * 256];
    #pragma unroll
    for (int i = 0; i < 8; i++) {
        __half2 h0 = __floats2half2_rn(v[i].x, v[i].y);
        __half2 h1 = __floats2half2_rn(v[i].z, v[i].w);
        *(uint2*)(out + (size_t)(base + i * 256) * 4) =
            make_uint2(*(uint32_t*)&h0, *(uint32_t*)&h1);
    }
}

// ---------------- rmsnorm -> fp16 ----------------
__global__ void rmsnorm_h_kernel(const float* __restrict__ x,
                                 const float* __restrict__ scale,
                                 __half* __restrict__ y)
{
    int row = blockIdx.x;
    const float4* xr = (const float4*)(x + (size_t)row * Cc);
    float4 v = xr[threadIdx.x];
    float ss = v.x*v.x + v.y*v.y + v.z*v.z + v.w*v.w;
    #pragma unroll
    for (int o = 16; o; o >>= 1) ss += __shfl_xor_sync(0xffffffffu, ss, o);
    __shared__ float wsum[8];
    if ((threadIdx.x & 31) == 0) wsum[threadIdx.x >> 5] = ss;
    __syncthreads();
    if (threadIdx.x < 8) {
        float t = wsum[threadIdx.x];
        #pragma unroll
        for (int o = 4; o; o >>= 1) t += __shfl_xor_sync(0xffu, t, o);
        if (threadIdx.x == 0) wsum[0] = t;
    }
    __syncthreads();
    float inv = rsqrtf(wsum[0] * (1.0f / Cc) + 1e-6f);
    float4 sc = ((const float4*)scale)[threadIdx.x];
    __half2 h0 = __floats2half2_rn(v.x * inv * (1.f + sc.x), v.y * inv * (1.f + sc.y));
    __half2 h1 = __floats2half2_rn(v.z * inv * (1.f + sc.z), v.w * inv * (1.f + sc.w));
    uint2 u = make_uint2(*(uint32_t*)&h0, *(uint32_t*)&h1);
    *(uint2*)(y + (size_t)row * Cc + threadIdx.x * 4) = u;
}

// ---------------- FP16 GEMM: A[M,K]@B[K,N], B native layout, trans-ldmatrix --
// MODE 0: C=acc (float)       MODE 1: C=acc+Res (float)
// MODE 3: C=silu(acc) (half)  MODE 4: C=acc*Res (half,half)  MODE 5: C=acc (half)
#define PAH 40
#define A_HBYTES (128*PAH*2)       // 10240
#define B_HBYTES (32*128*2)        // 8192
#define STAGE_HB (A_HBYTES + B_HBYTES)   // 18432
#define H_STAGES 4
#define HGEMM_SMEM (H_STAGES*STAGE_HB)   // 73728

template<int MODE, typename OT, typename RT>
__device__ __forceinline__ void hgemm_tile(
    const __half* __restrict__ A, const __half* __restrict__ Bkn,
    const RT* __restrict__ Res, OT* __restrict__ C,
    int NB, int NC, int K, int m0, int n0)
{
    extern __shared__ __half smh[];
    uint32_t smb;
    asm("{ .reg .u64 t; cvta.to.shared.u64 t, %1; cvt.u32.u64 %0, t; }"
        : "=r"(smb) : "l"(smh));

    int tid  = threadIdx.x;
    int lane = tid & 31, warp = tid >> 5;
    int wm = (warp & 1) * 64;
    int wn = (warp >> 1) * 32;
    int g = lane >> 2, c = lane & 3;
    int lane16 = lane & 15;
    int lhi = (lane & 16) >> 1;
    int m_ = lane >> 3, r_ = lane & 7;
    int tb = (m_ >> 1) * 8 + r_;       // k-row within 16-block for trans B

    uint32_t offA[4][2];
    #pragma unroll
    for (int mt = 0; mt < 4; mt++)
        #pragma unroll
        for (int ks = 0; ks < 2; ks++) {
            int row = wm + mt * 16 + lane16;
            int kx = ks * 16 + lhi;
            offA[mt][ks] = (uint32_t)(row * PAH + kx) * 2u;
        }
    uint32_t offB[2][2];
    #pragma unroll
    for (int bi = 0; bi < 2; bi++)
        #pragma unroll
        for (int ks = 0; ks < 2; ks++) {
            int k = ks * 16 + tb;
            int nch = (wn >> 3) + bi * 2 + (m_ & 1);
            offB[bi][ks] = (uint32_t)A_HBYTES + (uint32_t)(k * 256 + (((nch) ^ r_) << 4));
        }

    const __half* Ag = A + (size_t)m0 * K;

    float acc[4][4][4];
    #pragma unroll
    for (int i = 0; i < 4; i++)
        #pragma unroll
        for (int j = 0; j < 4; j++)
            #pragma unroll
            for (int r = 0; r < 4; r++) acc[i][j][r] = 0.f;

    int ntiles = K >> 5;

    int lra = tid >> 2, lca = tid & 3;
    int lrb = tid >> 3, lcb = (tid & 7) * 2;
    auto load_stage = [&](int s, int kc) {
        uint32_t base = smb + s * STAGE_HB;
        #pragma unroll
        for (int i = 0; i < 2; i++) {
            int r = lra + i * 64;
            CP16(base + r * 80 + lca * 16, Ag + (size_t)r * K + kc * 32 + lca * 8);
        }
        uint32_t bb = base + A_HBYTES;
        const __half* Bs = Bkn + (size_t)(kc * 32 + lrb) * NB + n0;
        #pragma unroll
        for (int i = 0; i < 2; i++) {
            int ch = lcb + i;
            CP16(bb + lrb * 256 + ((ch ^ (lrb & 7)) << 4), Bs + ch * 8);
        }
    };

    load_stage(0, 0); CP_COMMIT();
    load_stage(1, 1); CP_COMMIT();
    load_stage(2, 2); CP_COMMIT();

    for (int kt = 0; kt < ntiles; kt++) {
        asm volatile("cp.async.wait_group 2;");
        __syncthreads();

        int pf = kt + H_STAGES - 1;
        if (pf < ntiles) load_stage(pf % H_STAGES, pf);
        CP_COMMIT();

        uint32_t sbase = smb + (kt % H_STAGES) * STAGE_HB;
        #pragma unroll
        for (int ks = 0; ks < 2; ks++) {
            uint32_t bf[4][2];
            #pragma unroll
            for (int bi = 0; bi < 2; bi++) {
                uint32_t r[4];
                ldm_x4_t(r, sbase + offB[bi][ks]);
                bf[2 * bi][0] = r[0]; bf[2 * bi + 1][0] = r[1];
                bf[2 * bi][1] = r[2]; bf[2 * bi + 1][1] = r[3];
            }
            #pragma unroll
            for (int mt = 0; mt < 4; mt++) {
                uint32_t af[4];
                ldm_x4(af, sbase + offA[mt][ks]);
                #pragma unroll
                for (int nt = 0; nt < 4; nt++)
                    mma_f16(acc[mt][nt], af, bf[nt]);
            }
        }
    }

    #pragma unroll
    for (int mt = 0; mt < 4; mt++) {
        int r0 = m0 + wm + mt * 16 + g;
        #pragma unroll
        for (int nt = 0; nt < 4; nt++) {
            int cl = n0 + wn + nt * 8 + 2 * c;
            #pragma unroll
            for (int half_i = 0; half_i < 2; half_i++) {
                int rr = r0 + half_i * 8;
                float v0 = acc[mt][nt][half_i * 2 + 0];
                float v1 = acc[mt][nt][half_i * 2 + 1];
                size_t idx = (size_t)rr * NC + cl;
                if (MODE == 0) {
                    *(float2*)((float*)C + idx) = make_float2(v0, v1);
                } else if (MODE == 1) {
                    v0 += ((const float*)Res)[idx];
                    v1 += ((const float*)Res)[idx + 1];
                    *(float2*)((float*)C + idx) = make_float2(v0, v1);
                } else if (MODE == 3) {
                    v0 = v0 / (1.f + expf(-v0));
                    v1 = v1 / (1.f + expf(-v1));
                    *(__half2*)((__half*)C + idx) = __floats2half2_rn(v0, v1);
                } else if (MODE == 4) {
                    __half2 gh = *(const __half2*)((const __half*)Res + idx);
                    float2 gf = __half22float2(gh);
                    v0 *= gf.x; v1 *= gf.y;
                    *(__half2*)((__half*)C + idx) = __floats2half2_rn(v0, v1);
                } else if (MODE == 5) {
                    *(__half2*)((__half*)C + idx) = __floats2half2_rn(v0, v1);
                }
            }
        }
    }
}

template<int MODE, typename OT, typename RT>
__global__ __launch_bounds__(256, 2) void hgemm_kernel(
    const __half* __restrict__ A, const __half* __restrict__ Bkn,
    const RT* __restrict__ Res, OT* __restrict__ C, int N, int K)
{
    hgemm_tile<MODE, OT, RT>(A, Bkn, Res, C, N, N, K, blockIdx.y * 128, blockIdx.x * 128);
}

__global__ __launch_bounds__(256, 2) void qkv_h_kernel(
    const __half* __restrict__ A,
    const __half* __restrict__ Bq, const __half* __restrict__ Bk,
    const __half* __restrict__ Bv,
    __half* __restrict__ Cq, __half* __restrict__ Ck, __half* __restrict__ Cv,
    int K)
{
    int nb = blockIdx.x, m0 = blockIdx.y * 128;
    if (nb < 8)
        hgemm_tile<5, __half, float>(A, Bq, (const float*)nullptr, Cq, 1024, 1024, K, m0, nb * 128);
    else if (nb < 12)
        hgemm_tile<5, __half, float>(A, Bk, (const float*)nullptr, Ck, 512, 512, K, m0, (nb - 8) * 128);
    else
        hgemm_tile<5, __half, float>(A, Bv, (const float*)nullptr, Cv, 512, 512, K, m0, (nb - 12) * 128);
}

// ---------------- RoPE: fp16 in-place (+ q prescale) -------------------------
__global__ void rope_kernel(__half* __restrict__ q, __half* __restrict__ k)
{
    int row = blockIdx.x;
    int t = row & (Tt - 1);
    const float qscale = 0.08838834764831845f;
    __shared__ float s_sin[64], s_cos[64];
    if (threadIdx.x < 64) {
        float inv = expf(-logf(10000.0f) * (2.0f * threadIdx.x) / 128.0f);
        float ang = (float)t * inv;
        s_sin[threadIdx.x] = sinf(ang);
        s_cos[threadIdx.x] = cosf(ang);
    }
    __syncthreads();
    for (int p = threadIdx.x; p < 512; p += 256) {
        int head = p >> 6, i = p & 63;
        __half* base = q + (size_t)row * 1024 + head * 128;
        float x1 = __half2float(base[i]), x2 = __half2float(base[i + 64]);
        float s = s_sin[i], c = s_cos[i];
        base[i]      = __float2half_rn((x1 * c - x2 * s) * qscale);
        base[i + 64] = __float2half_rn((x2 * c + x1 * s) * qscale);
    }
    for (int p = threadIdx.x; p < 256; p += 256) {
        int head = p >> 6, i = p & 63;
        __half* base = k + (size_t)row * 512 + head * 128;
        float x1 = __half2float(base[i]), x2 = __half2float(base[i + 64]);
        float s = s_sin[i], c = s_cos[i];
        base[i]      = __float2half_rn(x1 * c - x2 * s);
        base[i + 64] = __float2half_rn(x2 * c + x1 * s);
    }
}

// ---------------- attention: 128-q tile, register Q/P, V via trans-ldmatrix --
// smem halves: Ks[2][64*128] @ 0,8192; Vs[2][64*128] @ 16384,24576
#define ATTN_SMEM (32768 * 2)   // 65536 B
__global__ __launch_bounds__(256, 1) void attn_kernel(
    const __half* __restrict__ Q, const __half* __restrict__ K,
    const __half* __restrict__ V, __half* __restrict__ O)
{
    extern __shared__ __half sma[];
    uint32_t smb;
    asm("{ .reg .u64 t; cvta.to.shared.u64 t, %1; cvt.u32.u64 %0, t; }"
        : "=r"(smb) : "l"(sma));

    int qb = blockIdx.x, h = blockIdx.y, b = blockIdx.z;
    int q0 = qb * 128;
    int tid = threadIdx.x, lane = tid & 31, warp = tid >> 5;
    int g = lane >> 2, c = lane & 3;
    int lane16 = lane & 15;
    int hb = (lane & 16) >> 4;
    int m_ = lane >> 3, r_ = lane & 7;
    int tb = (m_ >> 1) * 8 + r_;

    const __half* Qg = Q + (size_t)(b * Tt + q0 + 16 * warp) * 1024 + h * 128;
    uint32_t qf[8][4];
    #pragma unroll
    for (int ks = 0; ks < 8; ks++) {
        int kx = 16 * ks + 2 * c;
        qf[ks][0] = *(const uint32_t*)(Qg + (size_t)g * 1024 + kx);
        qf[ks][1] = *(const uint32_t*)(Qg + (size_t)(g + 8) * 1024 + kx);
        qf[ks][2] = *(const uint32_t*)(Qg + (size_t)g * 1024 + kx + 8);
        qf[ks][3] = *(const uint32_t*)(Qg + (size_t)(g + 8) * 1024 + kx + 8);
    }

    float Oacc[16][4];
    #pragma unroll
    for (int i = 0; i < 16; i++)
        #pragma unroll
        for (int j = 0; j < 4; j++) Oacc[i][j] = 0.f;
    float rm0 = -1e30f, rm1 = -1e30f, rl0 = 0.f, rl1 = 0.f;

    int kvh = h & 3;
    const __half* Kg = K + (size_t)b * Tt * 512 + kvh * 128;
    const __half* Vg = V + (size_t)b * Tt * 512 + kvh * 128;

    uint32_t voff[8];
    #pragma unroll
    for (int bi = 0; bi < 8; bi++) {
        int dch = bi * 2 + (m_ & 1);
        voff[bi] = (uint32_t)(tb * 128 + ((dch ^ r_) << 3)) * 2u;
    }

    int jlo = (2 * qb - 8 > 0) ? 2 * qb - 8 : 0;
    int jhi = 2 * qb + 1;

    auto load_kv = [&](int s, int k0) {
        #pragma unroll
        for (int p = 0; p < 4; p++) {
            int idx = tid + p * 256;
            int row = idx >> 4, ch = idx & 15;
            CP16(smb + (uint32_t)(s * 8192 + row * 128 + ((ch ^ (row & 7)) << 3)) * 2u,
                 Kg + (size_t)(k0 + row) * 512 + ch * 8);
        }
        #pragma unroll
        for (int p = 0; p < 4; p++) {
            int idx = tid + p * 256;
            int row = idx >> 4, ch = idx & 15;
            CP16(smb + (uint32_t)(16384 + s * 8192 + row * 128 + ((ch ^ (row & 7)) << 3)) * 2u,
                 Vg + (size_t)(k0 + row) * 512 + ch * 8);
        }
    };

    load_kv(0, jlo * 64); CP_COMMIT();

    int qt0 = q0 + 16 * warp + g;
    int qt1 = qt0 + 8;

    for (int jt = jlo; jt <= jhi; jt++) {
        int s = (jt - jlo) & 1;
        int k0 = jt * 64;

        asm volatile("cp.async.wait_group 0;");
        __syncthreads();
        if (jt < jhi) { load_kv(s ^ 1, k0 + 64); }
        CP_COMMIT();

        float sacc[8][4];
        #pragma unroll
        for (int i = 0; i < 8; i++)
            #pragma unroll
            for (int j = 0; j < 4; j++) sacc[i][j] = 0.f;
        #pragma unroll
        for (int ks = 0; ks < 8; ks++) {
            int chunk = 2 * ks + hb;
            uint32_t bf[8][2];
            #pragma unroll
            for (int bi = 0; bi < 4; bi++) {
                int colK = bi * 16 + lane16;
                uint32_t r[4];
                ldm_x4(r, smb + (uint32_t)(s * 8192 + colK * 128 +
                                           ((chunk ^ (colK & 7)) << 3)) * 2u);
                bf[2 * bi][0] = r[0]; bf[2 * bi + 1][0] = r[1];
                bf[2 * bi][1] = r[2]; bf[2 * bi + 1][1] = r[3];
            }
            #pragma unroll
            for (int nt = 0; nt < 8; nt++)
                mma_f16(sacc[nt], qf[ks], bf[nt]);
        }

        float pm0 = -INFINITY, pm1 = -INFINITY;
        #pragma unroll
        for (int nt = 0; nt < 8; nt++) {
            #pragma unroll
            for (int e = 0; e < 4; e++) {
                int ktg = k0 + nt * 8 + 2 * c + (e & 1);
                int qt = (e >> 1) ? qt1 : qt0;
                float sv = softcap50(sacc[nt][e]);
                bool ok = (ktg <= qt) && (qt - ktg < WINs);
                sv = ok ? sv : -INFINITY;
                sacc[nt][e] = sv;
                if (e >> 1) pm1 = fmaxf(pm1, sv); else pm0 = fmaxf(pm0, sv);
            }
        }
        pm0 = fmaxf(pm0, __shfl_xor_sync(0xffffffffu, pm0, 1));
        pm0 = fmaxf(pm0, __shfl_xor_sync(0xffffffffu, pm0, 2));
        pm1 = fmaxf(pm1, __shfl_xor_sync(0xffffffffu, pm1, 1));
        pm1 = fmaxf(pm1, __shfl_xor_sync(0xffffffffu, pm1, 2));

        float mn0 = fmaxf(rm0, pm0);
        float mn1 = fmaxf(rm1, pm1);
        float al0 = __expf(rm0 - mn0); rm0 = mn0;
        float al1 = __expf(rm1 - mn1); rm1 = mn1;

        uint32_t ph0[8], ph1[8];
        float ps0 = 0.f, ps1 = 0.f;
        #pragma unroll
        for (int nt = 0; nt < 8; nt++) {
            __half2 h0 = __floats2half2_rn(__expf(sacc[nt][0] - mn0),
                                           __expf(sacc[nt][1] - mn0));
            __half2 h1 = __floats2half2_rn(__expf(sacc[nt][2] - mn1),
                                           __expf(sacc[nt][3] - mn1));
            float2 f0 = __half22float2(h0), f1 = __half22float2(h1);
            ps0 += f0.x + f0.y;
            ps1 += f1.x + f1.y;
            ph0[nt] = *(uint32_t*)&h0;
            ph1[nt] = *(uint32_t*)&h1;
        }
        ps0 += __shfl_xor_sync(0xffffffffu, ps0, 1);
        ps0 += __shfl_xor_sync(0xffffffffu, ps0, 2);
        ps1 += __shfl_xor_sync(0xffffffffu, ps1, 1);
        ps1 += __shfl_xor_sync(0xffffffffu, ps1, 2);
        rl0 = rl0 * al0 + ps0;
        rl1 = rl1 * al1 + ps1;

        #pragma unroll
        for (int i = 0; i < 16; i++) {
            Oacc[i][0] *= al0; Oacc[i][1] *= al0;
            Oacc[i][2] *= al1; Oacc[i][3] *= al1;
        }

        uint32_t vstage = smb + (uint32_t)(16384 + s * 8192) * 2u;
        #pragma unroll
        for (int ks = 0; ks < 4; ks++) {
            uint32_t af[4] = { ph0[2 * ks], ph1[2 * ks], ph0[2 * ks + 1], ph1[2 * ks + 1] };
            uint32_t krow = (uint32_t)(ks * 16 * 128) * 2u;
            uint32_t vb[16][2];
            #pragma unroll
            for (int bi = 0; bi < 8; bi++) {
                uint32_t r[4];
                ldm_x4_t(r, vstage + krow + voff[bi]);
                vb[2 * bi][0] = r[0]; vb[2 * bi + 1][0] = r[1];
                vb[2 * bi][1] = r[2]; vb[2 * bi + 1][1] = r[3];
            }
            #pragma unroll
            for (int nt = 0; nt < 16; nt++)
                mma_f16(Oacc[nt], af, vb[nt]);
        }
    }

    float li0 = 1.f / rl0, li1 = 1.f / rl1;
    __half* Og = O + (size_t)(b * Tt + q0 + 16 * warp) * 1024 + h * 128;
    #pragma unroll
    for (int nt = 0; nt < 16; nt++) {
        int col = nt * 8 + 2 * c;
        *(__half2*)(Og + (size_t)g * 1024 + col) =
            __floats2half2_rn(Oacc[nt][0] * li0, Oacc[nt][1] * li0);
        *(__half2*)(Og + (size_t)(g + 8) * 1024 + col) =
            __floats2half2_rn(Oacc[nt][2] * li1, Oacc[nt][3] * li1);
    }
}

// ---------------- launch ----------------
extern "C" void kernel_launch(void* const* d_in, const int* in_sizes, int n_in,
                              void* d_out, int out_size)
{
    const float* x        = (const float*)d_in[0];
    const float* q_kernel = (const float*)d_in[1];
    const float* k_kernel = (const float*)d_in[2];
    const float* v_kernel = (const float*)d_in[3];
    const float* out_kern = (const float*)d_in[4];
    const float* attn_sc  = (const float*)d_in[5];
    const float* mlp_sc   = (const float*)d_in[6];
    const float* gate_k   = (const float*)d_in[7];
    const float* up_k     = (const float*)d_in[8];
    const float* down_k   = (const float*)d_in[9];
    float* out = (float*)d_out;

    __half *p_h, *p_attnh, *p_act, *p_qh, *p_kh, *p_vh, *p_gateh;
    float *p_x2;
    __half *w_q, *w_k, *w_v, *w_o, *w_g, *w_u, *w_d;
    cudaGetSymbolAddress((void**)&p_h,     g_h);
    cudaGetSymbolAddress((void**)&p_qh,    g_qh);
    cudaGetSymbolAddress((void**)&p_kh,    g_kh);
    cudaGetSymbolAddress((void**)&p_vh,    g_vh);
    cudaGetSymbolAddress((void**)&p_attnh, g_attnh);
    cudaGetSymbolAddress((void**)&p_x2,    g_x2);
    cudaGetSymbolAddress((void**)&p_gateh, g_gateh);
    cudaGetSymbolAddress((void**)&p_act,   g_act);
    cudaGetSymbolAddress((void**)&w_q,     g_wq);
    cudaGetSymbolAddress((void**)&w_k,     g_wk);
    cudaGetSymbolAddress((void**)&w_v,     g_wv);
    cudaGetSymbolAddress((void**)&w_o,     g_wo);
    cudaGetSymbolAddress((void**)&w_g,     g_wg);
    cudaGetSymbolAddress((void**)&w_u,     g_wu);
    cudaGetSymbolAddress((void**)&w_d,     g_wd);

    cudaFuncSetAttribute(attn_kernel, cudaFuncAttributeMaxDynamicSharedMemorySize, ATTN_SMEM);
    cudaFuncSetAttribute(qkv_h_kernel, cudaFuncAttributeMaxDynamicSharedMemorySize, HGEMM_SMEM);
    cudaFuncSetAttribute((hgemm_kernel<1, float, float>),   cudaFuncAttributeMaxDynamicSharedMemorySize, HGEMM_SMEM);
    cudaFuncSetAttribute((hgemm_kernel<3, __half, float>),  cudaFuncAttributeMaxDynamicSharedMemorySize, HGEMM_SMEM);
    cudaFuncSetAttribute((hgemm_kernel<4, __half, __half>), cudaFuncAttributeMaxDynamicSharedMemorySize, HGEMM_SMEM);

    // 0) all weights: single fused fp32 -> fp16 convert launch
    CvtArgs ca;
    ca.src[0] = (const float4*)q_kernel; ca.dst[0] = w_q;
    ca.src[1] = (const float4*)k_kernel; ca.dst[1] = w_k;
    ca.src[2] = (const float4*)v_kernel; ca.dst[2] = w_v;
    ca.src[3] = (const float4*)out_kern; ca.dst[3] = w_o;
    ca.src[4] = (const float4*)gate_k;   ca.dst[4] = w_g;
    ca.src[5] = (const float4*)up_k;     ca.dst[5] = w_u;
    ca.src[6] = (const float4*)down_k;   ca.dst[6] = w_d;
    cvt_all_kernel<<<1920, 256>>>(ca);

    // 1) h = rmsnorm(x, attn_scale) -> fp16
    rmsnorm_h_kernel<<<Mrows, 256>>>(x, attn_sc, p_h);
    // 2) fused q/k/v projections -> fp16
    qkv_h_kernel<<<dim3(16, 32), 256, HGEMM_SMEM>>>(p_h, w_q, w_k, w_v, p_qh, p_kh, p_vh, 1024);
    // 3) rope in-place on fp16 q (prescaled) and k
    rope_kernel<<<Mrows, 256>>>(p_qh, p_kh);
    // 4) attention
    attn_kernel<<<dim3(Tt / 128, Hh, Bb), 256, ATTN_SMEM>>>(p_qh, p_kh, p_vh, p_attnh);
    // 5) out projection + residual
    hgemm_kernel<1, float, float><<<dim3(8, 32), 256, HGEMM_SMEM>>>(p_attnh, w_o, x, p_x2, 1024, 1024);
    // 6) h = rmsnorm(x2, mlp_scale) -> fp16
    rmsnorm_h_kernel<<<Mrows, 256>>>(p_x2, mlp_sc, p_h);
    // 7) gate (silu, fp16), then up * gate -> fp16 act
    hgemm_kernel<3, __half, float><<<dim3(32, 32), 256, HGEMM_SMEM>>>(p_h, w_g, (const float*)nullptr, p_gateh, HIDm, 1024);
    hgemm_kernel<4, __half, __half><<<dim3(32, 32), 256, HGEMM_SMEM>>>(p_h, w_u, p_gateh, p_act, HIDm, 1024);
    // 8) down + residual -> out
    hgemm_kernel<1, float, float><<<dim3(8, 32), 256, HGEMM_SMEM>>>(p_act, w_d, p_x2, out, 1024, HIDm);
}